// round 2
// baseline (speedup 1.0000x reference)
#include <cuda_runtime.h>
#include <cuda_bf16.h>
#include <cstdint>

// Problem constants
#define BB 64          // batch
#define SS 2048        // seq len
#define HH 256         // hidden
#define J4 1024        // 4*H
#define HS_ELEMS 33554432ULL   // B*S*H

// 512 MB scratch for permuted xU: layout [t][g(16)][r(8)][jj(128)][bl(4)]
__device__ float g_xU[2048ULL * 64ULL * 1024ULL];

// ---------------------------------------------------------------------------
// helpers
// ---------------------------------------------------------------------------
__device__ __forceinline__ uint32_t s2u(const void* p) {
    return (uint32_t)__cvta_generic_to_shared(p);
}
__device__ __forceinline__ uint32_t mapa_u32(uint32_t saddr, uint32_t rank) {
    uint32_t r;
    asm("mapa.shared::cluster.u32 %0, %1, %2;" : "=r"(r) : "r"(saddr), "r"(rank));
    return r;
}
__device__ __forceinline__ void mbar_wait_cluster(uint32_t addr, uint32_t parity) {
    uint32_t done = 0;
    while (!done) {
        asm volatile(
            "{\n\t.reg .pred P;\n\t"
            "mbarrier.try_wait.parity.acquire.cluster.shared::cta.b64 P, [%1], %2, 0x989680;\n\t"
            "selp.b32 %0, 1, 0, P;\n\t}\n"
            : "=r"(done) : "r"(addr), "r"(parity) : "memory");
    }
}
__device__ __forceinline__ float sigm(float x) { return 1.f / (1.f + __expf(-x)); }
// accurate-enough tanh independent of fast-math flags; correct at +-inf
__device__ __forceinline__ float tanh_f(float x) {
    float e = __expf(2.f * x);
    return 1.f - 2.f / (e + 1.f);
}

// ---------------------------------------------------------------------------
// Kernel A: xUp[t][g][r][jj][bl] = bias[j] + sum_i x[b][t][i]*U_gate[i][m]
//   j = gate*256 + m, m = r*32 + (jj&31), gate = jj>>5, b = g*4+bl
// CTA tile: 128 rows (= 4 bl x 32 t) x 128 cols, K=256 in chunks of 32.
// grid = (8 colblk, 64 tblk, 16 g)  -- colblk fastest so the 8 CTAs sharing
// an x tile are bid-adjacent (same wave => x re-reads hit L2).
// 256 threads, 8x8 microtile.
// ---------------------------------------------------------------------------
__global__ __launch_bounds__(256)
void lstm_xu_kernel(const float* __restrict__ x,
                    const float* __restrict__ U0, const float* __restrict__ U1,
                    const float* __restrict__ U2, const float* __restrict__ U3,
                    const float* __restrict__ B0, const float* __restrict__ B1,
                    const float* __restrict__ B2, const float* __restrict__ B3)
{
    __shared__ __align__(16) float xs[32][132];   // [kk][row]
    __shared__ __align__(16) float us[32][132];   // [kk][col]

    const int cb   = blockIdx.x;   // 0..7   (128 cols each)
    const int tblk = blockIdx.y;   // 0..63  (32 t each)
    const int g    = blockIdx.z;   // 0..15
    const int gate = cb >> 1;
    const int mbase = (cb & 1) * 128;

    const float* Ug = (gate == 0) ? U0 : (gate == 1) ? U1 : (gate == 2) ? U2 : U3;
    const float* Bg = (gate == 0) ? B0 : (gate == 1) ? B1 : (gate == 2) ? B2 : B3;

    const int tid = threadIdx.x;
    const int tx = tid & 15;       // col group
    const int ty = tid >> 4;       // row group

    float C[8][8];
#pragma unroll
    for (int i = 0; i < 8; i++)
#pragma unroll
        for (int j = 0; j < 8; j++) C[i][j] = 0.f;

    for (int k0 = 0; k0 < 256; k0 += 32) {
        __syncthreads();
        // load x tile: lanes -> kk (contiguous gmem)
#pragma unroll
        for (int l = 0; l < 16; l++) {
            int e = l * 256 + tid;
            int kk = e & 31;
            int rr = e >> 5;           // 0..127
            int bl = rr >> 5, tt = rr & 31;
            int b = g * 4 + bl;
            int t = tblk * 32 + tt;
            xs[kk][rr] = x[((size_t)b * SS + t) * 256 + k0 + kk];
        }
        // load U tile: lanes -> cc (contiguous gmem)
#pragma unroll
        for (int l = 0; l < 16; l++) {
            int e = l * 256 + tid;
            int cc = e & 127;
            int kk = e >> 7;
            us[kk][cc] = Ug[(size_t)(k0 + kk) * 256 + mbase + cc];
        }
        __syncthreads();
#pragma unroll
        for (int kk = 0; kk < 32; kk++) {
            float4 xa = *(const float4*)&xs[kk][ty * 8];
            float4 xb = *(const float4*)&xs[kk][ty * 8 + 4];
            float4 ua = *(const float4*)&us[kk][tx * 8];
            float4 ub = *(const float4*)&us[kk][tx * 8 + 4];
            float A[8] = {xa.x, xa.y, xa.z, xa.w, xb.x, xb.y, xb.z, xb.w};
            float Bv[8] = {ua.x, ua.y, ua.z, ua.w, ub.x, ub.y, ub.z, ub.w};
#pragma unroll
            for (int i = 0; i < 8; i++)
#pragma unroll
                for (int j = 0; j < 8; j++)
                    C[i][j] = fmaf(A[i], Bv[j], C[i][j]);
        }
    }

    // epilogue: add bias, scatter to permuted layout
    float bias[8];
#pragma unroll
    for (int jc = 0; jc < 8; jc++) bias[jc] = Bg[mbase + tx * 8 + jc];

#pragma unroll
    for (int i = 0; i < 8; i++) {
        int rr = ty * 8 + i;
        int bl = rr >> 5, tt = rr & 31;
        int t = tblk * 32 + tt;
#pragma unroll
        for (int jc = 0; jc < 8; jc++) {
            int cc = tx * 8 + jc;
            int m = mbase + cc;
            int r = m >> 5;
            int jjj = gate * 32 + (m & 31);
            size_t dst = ((((size_t)t * 16 + g) * 8 + r) * 128 + jjj) * 4 + bl;
            g_xU[dst] = C[i][jc] + bias[jc];
        }
    }
}

// ---------------------------------------------------------------------------
// Kernel B: recurrence. 16 clusters x 8 CTAs. Cluster g owns batches 4g..4g+3.
// CTA r owns h-indices m in [32r, 32r+32) (all 4 gates => 128 z columns).
// V slice lives in registers (64 floats/thread, 512 threads).
// h replicated per-CTA in smem, exchanged via DSMEM + ping-pong mbarriers.
// Arrivals are warp-aggregated: 32 lanes store, __syncwarp, lane0 arrives on
// all 8 peers => 32 arrivals/mbar/step (vs 1024 unaggregated: ~1k cyc/step
// of single-address serialization avoided).
// ---------------------------------------------------------------------------
__global__ __launch_bounds__(512, 1) __cluster_dims__(8, 1, 1)
void lstm_rec_kernel(const float* __restrict__ Vi, const float* __restrict__ Vf,
                     const float* __restrict__ Vo, const float* __restrict__ Vc,
                     float* __restrict__ out, int tail)
{
    __shared__ __align__(16) float hbuf[2][256][4];   // [p][k][bl]
    __shared__ __align__(16) float pbuf[4][128][4];   // [ks][jj][bl]
    __shared__ __align__(16) float zbuf[128][4];      // [jj][bl]
    __shared__ __align__(8) unsigned long long mbar[2];

    const int tid = threadIdx.x;
    const int g = blockIdx.x >> 3;
    uint32_t r;
    asm("mov.u32 %0, %%cluster_ctarank;" : "=r"(r));

    const int ks = tid >> 7;          // k quarter (0..3)
    const int jj = tid & 127;         // z-column slot within CTA
    const int gate = jj >> 5;
    const int mlj = jj & 31;
    const int m_j = (int)r * 32 + mlj;  // V output column for this thread

    // --- load V slice into registers ---
    const float* Vg = (gate == 0) ? Vi : (gate == 1) ? Vf : (gate == 2) ? Vo : Vc;
    float Vreg[64];
#pragma unroll
    for (int kk = 0; kk < 64; kk++)
        Vreg[kk] = Vg[(size_t)(ks * 64 + kk) * 256 + m_j];

    // --- init h0 = 0, mbarriers (32 arrivals: 4 warps x 8 source CTAs) ---
    for (int i = tid; i < 1024; i += 512) ((float*)hbuf)[i] = 0.f;  // hbuf[0]
    if (tid == 0) {
        uint32_t a0 = s2u(&mbar[0]), a1 = s2u(&mbar[1]);
        asm volatile("mbarrier.init.shared.b64 [%0], %1;" :: "r"(a0), "r"(32u) : "memory");
        asm volatile("mbarrier.init.shared.b64 [%0], %1;" :: "r"(a1), "r"(32u) : "memory");
    }
    __syncthreads();
    asm volatile("barrier.cluster.arrive.aligned;" ::: "memory");
    asm volatile("barrier.cluster.wait.aligned;"   ::: "memory");

    // gate-stage identity (threads 0..127)
    const int bl = tid >> 5;      // 0..3   (valid for tid<128)
    const int ml = tid & 31;
    const int m  = (int)r * 32 + ml;
    float c = 0.f;

    const float4* xbase = (const float4*)g_xU + ((size_t)g * 8 + r) * 128;
    int ph0 = 0, ph1 = 0;

    for (int t = 0; t < SS; t++) {
        const int p = t & 1;

        // prefetch this step's xU block (issued before the wait; latency hidden)
        float4 xu = make_float4(0.f, 0.f, 0.f, 0.f);
        if (tid < 128) xu = xbase[(size_t)t * 16384 + jj];

        if (t) {
            uint32_t ma = s2u(&mbar[p]);
            if (p) { mbar_wait_cluster(ma, (uint32_t)ph1); ph1 ^= 1; }
            else   { mbar_wait_cluster(ma, (uint32_t)ph0); ph0 ^= 1; }
        }

        // matvec partial: acc[bl] += h[k] * V[k][j], k in this thread's quarter
        float4 acc = make_float4(0.f, 0.f, 0.f, 0.f);
        const float4* hrow = (const float4*)hbuf[p] + ks * 64;
#pragma unroll
        for (int kk = 0; kk < 64; kk++) {
            float4 h4 = hrow[kk];
            float v = Vreg[kk];
            acc.x = fmaf(h4.x, v, acc.x);
            acc.y = fmaf(h4.y, v, acc.y);
            acc.z = fmaf(h4.z, v, acc.z);
            acc.w = fmaf(h4.w, v, acc.w);
        }
        *(float4*)&pbuf[ks][jj][0] = acc;
        __syncthreads();

        // combine k-quarters + xU  -> z
        if (tid < 128) {
            float4 q0 = *(const float4*)&pbuf[0][jj][0];
            float4 q1 = *(const float4*)&pbuf[1][jj][0];
            float4 q2 = *(const float4*)&pbuf[2][jj][0];
            float4 q3 = *(const float4*)&pbuf[3][jj][0];
            float4 z;
            z.x = xu.x + q0.x + q1.x + q2.x + q3.x;
            z.y = xu.y + q0.y + q1.y + q2.y + q3.y;
            z.z = xu.z + q0.z + q1.z + q2.z + q3.z;
            z.w = xu.w + q0.w + q1.w + q2.w + q3.w;
            *(float4*)&zbuf[jj][0] = z;
        }
        __syncthreads();

        // gates + state update + publish h_new to all 8 CTAs
        if (tid < 128) {
            float zi = zbuf[ml][bl];
            float zf = zbuf[32 + ml][bl];
            float zo = zbuf[64 + ml][bl];
            float zg = zbuf[96 + ml][bl];
            float iv = sigm(zi);
            float fv = sigm(zf);
            float ov = sigm(zo);
            float gv = tanh_f(zg);
            c = fv * c + iv * gv;
            float hn = ov * tanh_f(c);

            // publish FIRST (unblocks remote CTAs), then the gmem store
            const int p2 = p ^ 1;
            uint32_t la = s2u(&hbuf[p2][m][bl]);
            uint32_t ma = s2u(&mbar[p2]);
#pragma unroll
            for (int pe = 0; pe < 8; pe++) {
                uint32_t ra = mapa_u32(la, (uint32_t)pe);
                asm volatile("st.shared::cluster.f32 [%0], %1;" :: "r"(ra), "f"(hn) : "memory");
            }
            __syncwarp();
            if ((tid & 31) == 0) {
#pragma unroll
                for (int pe = 0; pe < 8; pe++) {
                    uint32_t rma = mapa_u32(ma, (uint32_t)pe);
                    asm volatile("mbarrier.arrive.release.cluster.shared::cluster.b64 _, [%0];"
                                 :: "r"(rma) : "memory");
                }
            }

            out[(((size_t)(g * 4 + bl)) * SS + t) * 256 + m] = hn;
            if (tail && t == SS - 1) {
                out[HS_ELEMS + (size_t)(g * 4 + bl) * 256 + m] = hn;
                out[HS_ELEMS + 16384 + (size_t)(g * 4 + bl) * 256 + m] = c;
            }
        }
    }

    // keep all smem alive until every peer is done
    asm volatile("barrier.cluster.arrive.aligned;" ::: "memory");
    asm volatile("barrier.cluster.wait.aligned;"   ::: "memory");
}

// ---------------------------------------------------------------------------
extern "C" void kernel_launch(void* const* d_in, const int* in_sizes, int n_in,
                              void* d_out, int out_size)
{
    const float* x  = (const float*)d_in[0];
    const float* Ui = (const float*)d_in[1];
    const float* Vi = (const float*)d_in[2];
    const float* bi = (const float*)d_in[3];
    const float* Uf = (const float*)d_in[4];
    const float* Vf = (const float*)d_in[5];
    const float* bf = (const float*)d_in[6];
    const float* Uo = (const float*)d_in[7];
    const float* Vo = (const float*)d_in[8];
    const float* bo = (const float*)d_in[9];
    const float* Uc = (const float*)d_in[10];
    const float* Vc = (const float*)d_in[11];
    const float* bc = (const float*)d_in[12];
    float* out = (float*)d_out;

    const int tail = (out_size >= (int)(HS_ELEMS + 2ULL * BB * HH)) ? 1 : 0;

    dim3 gA(8, 64, 16);
    lstm_xu_kernel<<<gA, 256>>>(x, Ui, Uf, Uo, Uc, bi, bf, bo, bc);

    lstm_rec_kernel<<<128, 512>>>(Vi, Vf, Vo, Vc, out, tail);
}

// round 11
// speedup vs baseline: 1.3347x; 1.3347x over previous
#include <cuda_runtime.h>
#include <cuda_bf16.h>
#include <cstdint>

// Problem constants
#define BB 64          // batch
#define SS 2048        // seq len
#define HH 256         // hidden
#define HS_ELEMS 33554432ULL   // B*S*H

// 512 MB scratch for permuted xU: layout [t][g(16)][r(8)][jj(128)][bl(4)]
__device__ float g_xU[2048ULL * 64ULL * 1024ULL];

// ---------------------------------------------------------------------------
// helpers
// ---------------------------------------------------------------------------
__device__ __forceinline__ uint32_t s2u(const void* p) {
    return (uint32_t)__cvta_generic_to_shared(p);
}
__device__ __forceinline__ uint32_t mapa_u32(uint32_t saddr, uint32_t rank) {
    uint32_t r;
    asm("mapa.shared::cluster.u32 %0, %1, %2;" : "=r"(r) : "r"(saddr), "r"(rank));
    return r;
}
__device__ __forceinline__ void mbar_wait_cluster(uint32_t addr, uint32_t parity) {
    uint32_t done = 0;
    while (!done) {
        asm volatile(
            "{\n\t.reg .pred P;\n\t"
            "mbarrier.try_wait.parity.acquire.cluster.shared::cta.b64 P, [%1], %2, 0x989680;\n\t"
            "selp.b32 %0, 1, 0, P;\n\t}\n"
            : "=r"(done) : "r"(addr), "r"(parity) : "memory");
    }
}
__device__ __forceinline__ float sigm(float x) { return 1.f / (1.f + __expf(-x)); }
__device__ __forceinline__ float tanh_f(float x) {
    float e = __expf(2.f * x);
    return 1.f - 2.f / (e + 1.f);
}

// ---------------------------------------------------------------------------
// Kernel A: unchanged (measured ~2.05ms, at FFMA issue floor).
// xUp[t][g][r][jj][bl] = bias[j] + sum_i x[b][t][i]*U_gate[i][m]
// ---------------------------------------------------------------------------
__global__ __launch_bounds__(256)
void lstm_xu_kernel(const float* __restrict__ x,
                    const float* __restrict__ U0, const float* __restrict__ U1,
                    const float* __restrict__ U2, const float* __restrict__ U3,
                    const float* __restrict__ B0, const float* __restrict__ B1,
                    const float* __restrict__ B2, const float* __restrict__ B3)
{
    __shared__ __align__(16) float xs[32][132];   // [kk][row]
    __shared__ __align__(16) float us[32][132];   // [kk][col]

    const int cb   = blockIdx.x;   // 0..7
    const int tblk = blockIdx.y;   // 0..63
    const int g    = blockIdx.z;   // 0..15
    const int gate = cb >> 1;
    const int mbase = (cb & 1) * 128;

    const float* Ug = (gate == 0) ? U0 : (gate == 1) ? U1 : (gate == 2) ? U2 : U3;
    const float* Bg = (gate == 0) ? B0 : (gate == 1) ? B1 : (gate == 2) ? B2 : B3;

    const int tid = threadIdx.x;
    const int tx = tid & 15;
    const int ty = tid >> 4;

    float C[8][8];
#pragma unroll
    for (int i = 0; i < 8; i++)
#pragma unroll
        for (int j = 0; j < 8; j++) C[i][j] = 0.f;

    for (int k0 = 0; k0 < 256; k0 += 32) {
        __syncthreads();
#pragma unroll
        for (int l = 0; l < 16; l++) {
            int e = l * 256 + tid;
            int kk = e & 31;
            int rr = e >> 5;
            int bl = rr >> 5, tt = rr & 31;
            int b = g * 4 + bl;
            int t = tblk * 32 + tt;
            xs[kk][rr] = x[((size_t)b * SS + t) * 256 + k0 + kk];
        }
#pragma unroll
        for (int l = 0; l < 16; l++) {
            int e = l * 256 + tid;
            int cc = e & 127;
            int kk = e >> 7;
            us[kk][cc] = Ug[(size_t)(k0 + kk) * 256 + mbase + cc];
        }
        __syncthreads();
#pragma unroll
        for (int kk = 0; kk < 32; kk++) {
            float4 xa = *(const float4*)&xs[kk][ty * 8];
            float4 xb = *(const float4*)&xs[kk][ty * 8 + 4];
            float4 ua = *(const float4*)&us[kk][tx * 8];
            float4 ub = *(const float4*)&us[kk][tx * 8 + 4];
            float A[8] = {xa.x, xa.y, xa.z, xa.w, xb.x, xb.y, xb.z, xb.w};
            float Bv[8] = {ua.x, ua.y, ua.z, ua.w, ub.x, ub.y, ub.z, ub.w};
#pragma unroll
            for (int i = 0; i < 8; i++)
#pragma unroll
                for (int j = 0; j < 8; j++)
                    C[i][j] = fmaf(A[i], Bv[j], C[i][j]);
        }
    }

    float bias[8];
#pragma unroll
    for (int jc = 0; jc < 8; jc++) bias[jc] = Bg[mbase + tx * 8 + jc];

#pragma unroll
    for (int i = 0; i < 8; i++) {
        int rr = ty * 8 + i;
        int bl = rr >> 5, tt = rr & 31;
        int t = tblk * 32 + tt;
#pragma unroll
        for (int jc = 0; jc < 8; jc++) {
            int cc = tx * 8 + jc;
            int m = mbase + cc;
            int r = m >> 5;
            int jjj = gate * 32 + (m & 31);
            size_t dst = ((((size_t)t * 16 + g) * 8 + r) * 128 + jjj) * 4 + bl;
            g_xU[dst] = C[i][jc] + bias[jc];
        }
    }
}

// ---------------------------------------------------------------------------
// Kernel B: recurrence, warp-specialized.
// 16 clusters x 8 CTAs. Cluster g owns batches 4g..4g+3.
// Threads 0..511  : compute warps. ks = tid>>7 (k quarter), jj = tid&127.
//                   Vreg[64] in registers; 102-reg cap fits (~94 live) since
//                   gate/publish code lives in the other branch (R2 spilled
//                   at the 128-reg cap with joint allocation).
// Threads 512..639: gate warps. gt = tid-512 (0..127). prefetch xU -> bar1 ->
//                   combine -> gates -> DSMEM publish -> bar2 -> 8 threads
//                   issue 1 release-arrive each -> out STG.
// mbar arrive count = 8 (one per source CTA).
// ---------------------------------------------------------------------------
__global__ __launch_bounds__(640, 1) __cluster_dims__(8, 1, 1)
void lstm_rec_kernel(const float* __restrict__ Vi, const float* __restrict__ Vf,
                     const float* __restrict__ Vo, const float* __restrict__ Vc,
                     float* __restrict__ out, int tail)
{
    __shared__ __align__(16) float hbuf[2][256][4];   // [p][k][bl]
    __shared__ __align__(16) float pbuf[4][128][4];   // [ks][jj][bl]
    __shared__ __align__(16) float zbuf[128][4];      // [jj][bl]
    __shared__ __align__(8) unsigned long long mbar[2];

    const int tid = threadIdx.x;
    const int g = blockIdx.x >> 3;
    uint32_t r;
    asm("mov.u32 %0, %%cluster_ctarank;" : "=r"(r));

    // --- shared init ---
    for (int i = tid; i < 1024; i += 640) ((float*)hbuf)[i] = 0.f;  // hbuf[0]
    if (tid == 0) {
        uint32_t a0 = s2u(&mbar[0]), a1 = s2u(&mbar[1]);
        asm volatile("mbarrier.init.shared.b64 [%0], %1;" :: "r"(a0), "r"(8u) : "memory");
        asm volatile("mbarrier.init.shared.b64 [%0], %1;" :: "r"(a1), "r"(8u) : "memory");
    }
    __syncthreads();
    asm volatile("barrier.cluster.arrive.aligned;" ::: "memory");
    asm volatile("barrier.cluster.wait.aligned;"   ::: "memory");

    if (tid < 512) {
        // ================= compute warps =================
        const int ks = tid >> 7;          // k quarter (0..3)
        const int jj = tid & 127;         // z-column slot within CTA
        const int gate = jj >> 5;
        const int m_j = (int)r * 32 + (jj & 31);

        const float* Vg = (gate == 0) ? Vi : (gate == 1) ? Vf : (gate == 2) ? Vo : Vc;
        float Vreg[64];
#pragma unroll
        for (int kk = 0; kk < 64; kk++)
            Vreg[kk] = Vg[(size_t)(ks * 64 + kk) * 256 + m_j];

        float* pdst = &pbuf[ks][jj][0];
        const uint32_t ma0 = s2u(&mbar[0]);   // hoisted out of loop
        const uint32_t ma1 = s2u(&mbar[1]);
        int ph0 = 0, ph1 = 0;

        for (int t = 0; t < SS; t++) {
            const int p = t & 1;
            if (t) {
                if (p) { mbar_wait_cluster(ma1, (uint32_t)ph1); ph1 ^= 1; }
                else   { mbar_wait_cluster(ma0, (uint32_t)ph0); ph0 ^= 1; }
            }
            float4 acc = make_float4(0.f, 0.f, 0.f, 0.f);
            const float4* hrow = (const float4*)hbuf[p] + ks * 64;
#pragma unroll
            for (int kk = 0; kk < 64; kk++) {
                float4 h4 = hrow[kk];
                float v = Vreg[kk];
                acc.x = fmaf(h4.x, v, acc.x);
                acc.y = fmaf(h4.y, v, acc.y);
                acc.z = fmaf(h4.z, v, acc.z);
                acc.w = fmaf(h4.w, v, acc.w);
            }
            *(float4*)pdst = acc;
            asm volatile("bar.sync 1, 640;" ::: "memory");
        }
    } else {
        // ================= gate warps =================
        const int gt = tid - 512;         // 0..127
        const int bl = gt >> 5;
        const int ml = gt & 31;
        const int m  = (int)r * 32 + ml;
        float c = 0.f;

        const float4* xbase = (const float4*)g_xU + ((size_t)g * 8 + r) * 128;
        float* obase = out + (((size_t)(g * 4 + bl)) * SS) * 256 + m;

        // hoisted remote addresses (mapa results are loop-invariant)
        uint32_t ra0[8], ra1[8];
        {
            uint32_t la0 = s2u(&hbuf[0][m][bl]);
            uint32_t la1 = s2u(&hbuf[1][m][bl]);
#pragma unroll
            for (int pe = 0; pe < 8; pe++) {
                ra0[pe] = mapa_u32(la0, (uint32_t)pe);
                ra1[pe] = mapa_u32(la1, (uint32_t)pe);
            }
        }
        uint32_t rmb0 = 0, rmb1 = 0;
        if (gt < 8) {
            rmb0 = mapa_u32(s2u(&mbar[0]), (uint32_t)gt);
            rmb1 = mapa_u32(s2u(&mbar[1]), (uint32_t)gt);
        }

        for (int t = 0; t < SS; t++) {
            const int p = t & 1;
            // prefetch this step's xU block; consumed after bar1 (~2000cyc later)
            float4 xu = xbase[(size_t)t * 16384 + gt];

            asm volatile("bar.sync 1, 640;" ::: "memory");

            // combine k-quarters + xU -> z (this thread owns column slot gt)
            float4 q0 = *(const float4*)&pbuf[0][gt][0];
            float4 q1 = *(const float4*)&pbuf[1][gt][0];
            float4 q2 = *(const float4*)&pbuf[2][gt][0];
            float4 q3 = *(const float4*)&pbuf[3][gt][0];
            float4 z;
            z.x = xu.x + q0.x + q1.x + q2.x + q3.x;
            z.y = xu.y + q0.y + q1.y + q2.y + q3.y;
            z.z = xu.z + q0.z + q1.z + q2.z + q3.z;
            z.w = xu.w + q0.w + q1.w + q2.w + q3.w;
            *(float4*)&zbuf[gt][0] = z;
            asm volatile("bar.sync 2, 128;" ::: "memory");

            // gates + state update (this thread owns state (m, bl))
            float zi = zbuf[ml][bl];
            float zf = zbuf[32 + ml][bl];
            float zo = zbuf[64 + ml][bl];
            float zg = zbuf[96 + ml][bl];
            float iv = sigm(zi);
            float fv = sigm(zf);
            float ov = sigm(zo);
            float gv = tanh_f(zg);
            c = fv * c + iv * gv;
            float hn = ov * tanh_f(c);

            // publish h_new to all 8 CTAs' hbuf[p^1]
#pragma unroll
            for (int pe = 0; pe < 8; pe++) {
                uint32_t ra = p ? ra0[pe] : ra1[pe];   // p2 = p^1
                asm volatile("st.shared::cluster.f32 [%0], %1;" :: "r"(ra), "f"(hn) : "memory");
            }
            asm volatile("bar.sync 2, 128;" ::: "memory");
            if (gt < 8) {
                // thread gt arrives (release) on peer gt's mbar[p^1]: 8 arrivals
                // per destination mbar (one per source CTA), issued in parallel.
                uint32_t rma = p ? rmb0 : rmb1;
                asm volatile("mbarrier.arrive.release.cluster.shared::cluster.b64 _, [%0];"
                             :: "r"(rma) : "memory");
            }

            obase[(size_t)t * 256] = hn;
            if (tail && t == SS - 1) {
                out[HS_ELEMS + (size_t)(g * 4 + bl) * 256 + m] = hn;
                out[HS_ELEMS + 16384 + (size_t)(g * 4 + bl) * 256 + m] = c;
            }
        }
    }

    // keep all smem alive until every peer is done
    asm volatile("barrier.cluster.arrive.aligned;" ::: "memory");
    asm volatile("barrier.cluster.wait.aligned;"   ::: "memory");
}

// ---------------------------------------------------------------------------
extern "C" void kernel_launch(void* const* d_in, const int* in_sizes, int n_in,
                              void* d_out, int out_size)
{
    const float* x  = (const float*)d_in[0];
    const float* Ui = (const float*)d_in[1];
    const float* Vi = (const float*)d_in[2];
    const float* bi = (const float*)d_in[3];
    const float* Uf = (const float*)d_in[4];
    const float* Vf = (const float*)d_in[5];
    const float* bf = (const float*)d_in[6];
    const float* Uo = (const float*)d_in[7];
    const float* Vo = (const float*)d_in[8];
    const float* bo = (const float*)d_in[9];
    const float* Uc = (const float*)d_in[10];
    const float* Vc = (const float*)d_in[11];
    const float* bc = (const float*)d_in[12];
    float* out = (float*)d_out;

    const int tail = (out_size >= (int)(HS_ELEMS + 2ULL * BB * HH)) ? 1 : 0;

    dim3 gA(8, 64, 16);
    lstm_xu_kernel<<<gA, 256>>>(x, Ui, Uf, Uo, Uc, bi, bf, bo, bc);

    lstm_rec_kernel<<<128, 640>>>(Vi, Vf, Vo, Vc, out, tail);
}